// round 2
// baseline (speedup 1.0000x reference)
#include <cuda_runtime.h>
#include <math.h>

// ---------------------------------------------------------------------------
// Problem constants
// ---------------------------------------------------------------------------
#define N_TL   32768   // timeline sequences
#define T_TL   32      // timeline seq len
#define B_SZ   512     // batch
#define T_TX   64      // text seq len
#define E_DIM  50      // embedding
#define H_DIM  32      // rnn hidden

// ---------------------------------------------------------------------------
// Scratch (static device globals; no runtime allocation allowed).
// Referenced directly from kernels — no cudaGetSymbolAddress in kernel_launch.
// ---------------------------------------------------------------------------
__device__ float g_h2[(size_t)N_TL * 64];   // timeline RNN final hidden [N, 2H]  (8 MB)
__device__ float g_hn[(size_t)B_SZ * 64];   // text RNN final hidden [B, 2H]
__device__ float g_red[(size_t)B_SZ * 192]; // per-batch [mean(64) | min(64) | max(64)]

// ---------------------------------------------------------------------------
// Fast tanh: (e^{2x}-1)/(e^{2x}+1) with MUFU ex2/rcp path. |err| ~1e-6.
// ---------------------------------------------------------------------------
__device__ __forceinline__ float tanh_fast(float x) {
    x = fminf(fmaxf(x, -20.0f), 20.0f);
    float e = __expf(2.0f * x);
    return __fdividef(e - 1.0f, e + 1.0f);
}

// ---------------------------------------------------------------------------
// Bidirectional Elman RNN, warp-per-(sequence, direction).
//  - Each lane j owns output unit j: Wi row (50, padded to 52) + Whh row (32)
//    live in registers.
//  - The sequence's inputs are staged once into smem (rows padded to 52 floats
//    so float4 loads are aligned); both direction-warps of a pair share it.
//  - h is broadcast per step through a double-buffered per-warp smem buffer
//    read as float4 (broadcast, conflict-free): one __syncwarp per step.
//  - 4 independent accumulators break the serial FMA chain (lat 4).
// OUT_TL selects which scratch the result goes to (no pointer args needed,
// but we keep the pointer arg for flexibility between g_h2 / g_hn).
// ---------------------------------------------------------------------------
template <int TSTEPS, int PAIRS, bool TO_TL>
__global__ __launch_bounds__(PAIRS * 64)
void rnn_kernel(const float* __restrict__ X,
                const float* __restrict__ wif, const float* __restrict__ whf,
                const float* __restrict__ bif, const float* __restrict__ bhf,
                const float* __restrict__ wib, const float* __restrict__ whb,
                const float* __restrict__ bib, const float* __restrict__ bhb,
                int nseq)
{
    __shared__ __align__(16) float xs[PAIRS][TSTEPS][52];
    __shared__ __align__(16) float hbuf[2][PAIRS * 2][32];

    const int tid  = threadIdx.x;
    const int w    = tid >> 5;
    const int lane = tid & 31;
    const int p    = w >> 1;      // pair (sequence) index within block
    const int dir  = w & 1;       // 0 = forward, 1 = backward
    const int n    = blockIdx.x * PAIRS + p;

    // Cooperative staging of this pair's input sequence (64 threads per pair).
    {
        const int q = tid - p * 64;
        const float* xg = X + (size_t)n * (TSTEPS * E_DIM);
        for (int i = q; i < TSTEPS * 52; i += 64) {
            int t = i / 52;
            int e = i - t * 52;
            xs[p][t][e] = (e < E_DIM) ? xg[t * E_DIM + e] : 0.0f;
        }
    }
    __syncthreads();

    const float* wi = dir ? wib : wif;
    const float* wh = dir ? whb : whf;
    const float* bi = dir ? bib : bif;
    const float* bh = dir ? bhb : bhf;

    // Per-lane weight rows into registers.
    float Wi[52];
#pragma unroll
    for (int e = 0; e < E_DIM; e++) Wi[e] = __ldg(&wi[lane * E_DIM + e]);
    Wi[50] = 0.0f; Wi[51] = 0.0f;
    float Wh[32];
#pragma unroll
    for (int k = 0; k < H_DIM; k++) Wh[k] = __ldg(&wh[lane * H_DIM + k]);
    const float bias = __ldg(&bi[lane]) + __ldg(&bh[lane]);

    float h = 0.0f;
#pragma unroll 1
    for (int s = 0; s < TSTEPS; s++) {
        const int t   = dir ? (TSTEPS - 1 - s) : s;
        const int par = s & 1;
        hbuf[par][w][lane] = h;
        __syncwarp();

        float a0 = bias, a1 = 0.0f, a2 = 0.0f, a3 = 0.0f;
        const float4* xr = reinterpret_cast<const float4*>(xs[p][t]);
#pragma unroll
        for (int q4 = 0; q4 < 13; q4++) {
            float4 v = xr[q4];
            a0 = fmaf(v.x, Wi[4 * q4 + 0], a0);
            a1 = fmaf(v.y, Wi[4 * q4 + 1], a1);
            a2 = fmaf(v.z, Wi[4 * q4 + 2], a2);
            a3 = fmaf(v.w, Wi[4 * q4 + 3], a3);
        }
        const float4* hr = reinterpret_cast<const float4*>(hbuf[par][w]);
#pragma unroll
        for (int q4 = 0; q4 < 8; q4++) {
            float4 v = hr[q4];
            a0 = fmaf(v.x, Wh[4 * q4 + 0], a0);
            a1 = fmaf(v.y, Wh[4 * q4 + 1], a1);
            a2 = fmaf(v.z, Wh[4 * q4 + 2], a2);
            a3 = fmaf(v.w, Wh[4 * q4 + 3], a3);
        }
        h = tanh_fast((a0 + a1) + (a2 + a3));
        // next step writes hbuf[par^1]: no trailing sync needed (double buffer)
    }

    float* out = TO_TL ? g_h2 : g_hn;
    if (n < nseq)
        out[(size_t)n * 64 + dir * 32 + lane] = h;
}

// ---------------------------------------------------------------------------
// Ragged segment mean/min/max over g_h2. One block per batch row, 64 threads
// (one per hidden column). Segment offset = prefix sum of timeline_elements.
// ---------------------------------------------------------------------------
__global__ void seg_reduce_kernel(const int* __restrict__ te)
{
    const int b = blockIdx.x;
    const int c = threadIdx.x;   // 0..63
    __shared__ int s_off;
    if (c == 0) {
        int o = 0;
        for (int i = 0; i < b; i++) o += te[i];
        s_off = o;
    }
    __syncthreads();
    const int cnt = te[b];
    const float* hp = g_h2 + (size_t)s_off * 64 + c;
    float sm = 0.0f, mn = 3.402823466e38f, mx = -3.402823466e38f;
    for (int r = 0; r < cnt; r++) {
        float v = hp[(size_t)r * 64];
        sm += v;
        mn = fminf(mn, v);
        mx = fmaxf(mx, v);
    }
    const float inv = (cnt > 0) ? __fdividef(1.0f, (float)cnt) : 0.0f;
    g_red[b * 192 + c]       = sm * inv;
    g_red[b * 192 + 64 + c]  = mn;
    g_red[b * 192 + 128 + c] = mx;
}

// ---------------------------------------------------------------------------
// Head: x = [h_n(64) | normal(49) | mean(64) | min(64) | max(64)] (305)
//       y = tanh(x @ fc1_w.T + fc1_b); out = sigmoid(y @ fc2_w.T + fc2_b)
// One warp per batch row; lane j computes fc1 unit j; warp-reduce for fc2.
// ---------------------------------------------------------------------------
__global__ __launch_bounds__(256)
void head_kernel(const float* __restrict__ nf,
                 const float* __restrict__ fc1_w, const float* __restrict__ fc1_b,
                 const float* __restrict__ fc2_w, const float* __restrict__ fc2_b,
                 float* __restrict__ out)
{
    __shared__ float xr[8][308];
    const int tid  = threadIdx.x;
    const int w    = tid >> 5;
    const int lane = tid & 31;
    const int row  = blockIdx.x * 8 + w;

    for (int i = lane; i < 305; i += 32) {
        float v;
        if (i < 64)        v = g_hn[(size_t)row * 64 + i];
        else if (i < 113)  v = nf[(size_t)row * 49 + (i - 64)];
        else               v = g_red[(size_t)row * 192 + (i - 113)];
        xr[w][i] = v;
    }
    __syncwarp();

    const float* wrow = fc1_w + (size_t)lane * 305;
    float a0 = 0.0f, a1 = 0.0f, a2 = 0.0f, a3 = 0.0f;
    int k = 0;
    for (; k + 4 <= 304; k += 4) {
        a0 = fmaf(__ldg(&wrow[k + 0]), xr[w][k + 0], a0);
        a1 = fmaf(__ldg(&wrow[k + 1]), xr[w][k + 1], a1);
        a2 = fmaf(__ldg(&wrow[k + 2]), xr[w][k + 2], a2);
        a3 = fmaf(__ldg(&wrow[k + 3]), xr[w][k + 3], a3);
    }
    for (; k < 305; k++) a0 = fmaf(__ldg(&wrow[k]), xr[w][k], a0);

    float y = tanh_fast(((a0 + a1) + (a2 + a3)) + __ldg(&fc1_b[lane]));
    float z = y * __ldg(&fc2_w[lane]);
#pragma unroll
    for (int o = 16; o > 0; o >>= 1) z += __shfl_xor_sync(0xffffffffu, z, o);
    if (lane == 0)
        out[row] = __fdividef(1.0f, 1.0f + __expf(-(z + __ldg(&fc2_b[0]))));
}

// ---------------------------------------------------------------------------
// Launch. Input ordering is disambiguated at runtime: setup_inputs dict order
// has timeline_elements (size 512) at index 3; reference-signature order has
// rnn1_wif (size 1600) there and timeline_elements last.
// Pure kernel launches — fully graph-capturable.
// ---------------------------------------------------------------------------
extern "C" void kernel_launch(void* const* d_in, const int* in_sizes, int n_in,
                              void* d_out, int out_size)
{
    int base_r1, base_r2, base_fc, idx_te;
    if (in_sizes[3] == B_SZ) {          // setup_inputs order
        idx_te = 3;  base_r1 = 4;  base_r2 = 12; base_fc = 20;
    } else {                            // reference signature order
        base_r1 = 3; base_r2 = 11; base_fc = 19; idx_te = n_in - 1;
    }

    const float* nf  = (const float*)d_in[0];
    const float* tf  = (const float*)d_in[1];
    const float* ttf = (const float*)d_in[2];
    const int*   te  = (const int*)d_in[idx_te];
#define FPTR(i) ((const float*)d_in[(i)])

    // Timeline RNN: 32768 seqs, 4 per block (8 warps), 8192 blocks.
    rnn_kernel<T_TL, 4, true><<<N_TL / 4, 256>>>(
        ttf,
        FPTR(base_r2 + 0), FPTR(base_r2 + 1), FPTR(base_r2 + 2), FPTR(base_r2 + 3),
        FPTR(base_r2 + 4), FPTR(base_r2 + 5), FPTR(base_r2 + 6), FPTR(base_r2 + 7),
        N_TL);

    // Text RNN: 512 seqs, 2 per block (4 warps), 256 blocks.
    rnn_kernel<T_TX, 2, false><<<B_SZ / 2, 128>>>(
        tf,
        FPTR(base_r1 + 0), FPTR(base_r1 + 1), FPTR(base_r1 + 2), FPTR(base_r1 + 3),
        FPTR(base_r1 + 4), FPTR(base_r1 + 5), FPTR(base_r1 + 6), FPTR(base_r1 + 7),
        B_SZ);

    // Segment mean/min/max.
    seg_reduce_kernel<<<B_SZ, 64>>>(te);

    // Head (fc1 tanh -> fc2 sigmoid).
    head_kernel<<<B_SZ / 8, 256>>>(
        nf,
        FPTR(base_fc + 0), FPTR(base_fc + 1), FPTR(base_fc + 2), FPTR(base_fc + 3),
        (float*)d_out);
#undef FPTR
}

// round 3
// speedup vs baseline: 1.2382x; 1.2382x over previous
#include <cuda_runtime.h>
#include <math.h>

// ---------------------------------------------------------------------------
// Problem constants
// ---------------------------------------------------------------------------
#define N_TL   32768   // timeline sequences
#define T_TL   32      // timeline seq len
#define B_SZ   512     // batch
#define T_TX   64      // text seq len
#define E_DIM  50      // embedding
#define H_DIM  32      // rnn hidden

// ---------------------------------------------------------------------------
// Scratch (static device globals; no runtime allocation allowed)
// ---------------------------------------------------------------------------
__device__ float g_h2[(size_t)N_TL * 64];   // timeline RNN final hidden [N, 2H]
__device__ float g_hn[(size_t)B_SZ * 64];   // text RNN final hidden [B, 2H]
__device__ float g_red[(size_t)B_SZ * 192]; // per-batch [mean | min | max]

// ---------------------------------------------------------------------------
// Fast tanh (validated rel_err 6e-8 end to end in R2)
// ---------------------------------------------------------------------------
__device__ __forceinline__ float tanh_fast(float x) {
    x = fminf(fmaxf(x, -20.0f), 20.0f);
    float e = __expf(2.0f * x);
    return __fdividef(e - 1.0f, e + 1.0f);
}

// ===========================================================================
// TIMELINE RNN — warp = one sequence, both directions fused.
//   lanes 0..15  : forward,  units u and u+16  (u = lane & 15)
//   lanes 16..31 : backward, units u and u+16
// Each dual-broadcast LDS.128 (fwd half reads x[t], bwd half x[31-t]) feeds
// 2 FMAs per lane -> MIO bytes per FLOP halved vs R2. Weights live in regs
// and are amortized over many sequences via persistent grid-stride warps.
// x rows padded to 56 floats (16B-aligned rows; odd*24 bank offset between
// the two halves' rows -> provably conflict-free dual broadcasts).
// ===========================================================================
#define XROW 56
#define HSTR 36   // offset of bwd h block inside a parity buffer (banks shifted by 4)

__global__ __launch_bounds__(64, 4)
void timeline_rnn_kernel(const float* __restrict__ X,
                         const float* __restrict__ wif, const float* __restrict__ whf,
                         const float* __restrict__ bif, const float* __restrict__ bhf,
                         const float* __restrict__ wib, const float* __restrict__ whb,
                         const float* __restrict__ bib, const float* __restrict__ bhb)
{
    __shared__ __align__(16) float xs[2][2][T_TL * XROW]; // [warp][buf][row*56]
    __shared__ __align__(16) float hsm[2][2 * 72];        // [warp][parity*72 + dir*36 + unit]

    const int lane  = threadIdx.x & 31;
    const int wlocal= threadIdx.x >> 5;          // 0..1
    const int half  = lane >> 4;                 // 0 = fwd, 1 = bwd
    const int u     = lane & 15;                 // first owned unit
    const int dofs  = half * HSTR;

    const int gwarp  = blockIdx.x * 2 + wlocal;
    const int stride = gridDim.x * 2;

    // ---- weights for this lane's direction, rows u and u+16, in registers
    const float* wi = half ? wib : wif;
    const float* wh = half ? whb : whf;
    const float* bi = half ? bib : bif;
    const float* bh = half ? bhb : bhf;

    float Wi0[E_DIM], Wi1[E_DIM];
#pragma unroll
    for (int e = 0; e < E_DIM; e++) {
        Wi0[e] = __ldg(wi + u * E_DIM + e);
        Wi1[e] = __ldg(wi + (u + 16) * E_DIM + e);
    }
    float Wh0[H_DIM], Wh1[H_DIM];
#pragma unroll
    for (int k = 0; k < H_DIM; k++) {
        Wh0[k] = __ldg(wh + u * H_DIM + k);
        Wh1[k] = __ldg(wh + (u + 16) * H_DIM + k);
    }
    const float b0v = __ldg(bi + u)      + __ldg(bh + u);
    const float b1v = __ldg(bi + u + 16) + __ldg(bh + u + 16);

    float* xw = &xs[wlocal][0][0];
    float* hw = &hsm[wlocal][0];

    // ---- prefetch first sequence into buffer 0
    int n = gwarp;
    if (n < N_TL) {
        const float* xg = X + (size_t)n * (T_TL * E_DIM);
        for (int i = lane; i < T_TL * E_DIM; i += 32) {
            int r = i / E_DIM, c = i - r * E_DIM;
            xw[r * XROW + c] = __ldg(xg + i);
        }
    }
    int buf = 0;

    for (; n < N_TL; n += stride) {
        // prefetch next sequence into the other buffer (overlaps with compute)
        int n2 = n + stride;
        if (n2 < N_TL) {
            const float* xg = X + (size_t)n2 * (T_TL * E_DIM);
            float* xd = xw + (buf ^ 1) * (T_TL * XROW);
            for (int i = lane; i < T_TL * E_DIM; i += 32) {
                int r = i / E_DIM, c = i - r * E_DIM;
                xd[r * XROW + c] = __ldg(xg + i);
            }
        }
        __syncwarp();    // current buffer's staging (prev iter) visible

        // init h parity-0
        hw[dofs + u]      = 0.0f;
        hw[dofs + u + 16] = 0.0f;
        __syncwarp();

        const float* xb = xw + buf * (T_TL * XROW);
        float h0 = 0.0f, h1 = 0.0f;

#pragma unroll 1
        for (int s = 0; s < T_TL; s++) {
            const int p   = s & 1;
            const int row = half ? (T_TL - 1 - s) : s;   // per-half x row
            const float4* xr = reinterpret_cast<const float4*>(xb + row * XROW);
            const float4* hr = reinterpret_cast<const float4*>(hw + p * 72 + dofs);

            float a0 = b0v, a1 = 0.0f;   // unit u
            float c0 = b1v, c1 = 0.0f;   // unit u+16
#pragma unroll
            for (int q = 0; q < 12; q++) {
                float4 v = xr[q];
                a0 = fmaf(v.x, Wi0[4 * q + 0], a0);
                a1 = fmaf(v.y, Wi0[4 * q + 1], a1);
                a0 = fmaf(v.z, Wi0[4 * q + 2], a0);
                a1 = fmaf(v.w, Wi0[4 * q + 3], a1);
                c0 = fmaf(v.x, Wi1[4 * q + 0], c0);
                c1 = fmaf(v.y, Wi1[4 * q + 1], c1);
                c0 = fmaf(v.z, Wi1[4 * q + 2], c0);
                c1 = fmaf(v.w, Wi1[4 * q + 3], c1);
            }
            {   // tail: cols 48,49 only (50,51 are unwritten smem -> never used)
                float4 v = xr[12];
                a0 = fmaf(v.x, Wi0[48], a0);
                a1 = fmaf(v.y, Wi0[49], a1);
                c0 = fmaf(v.x, Wi1[48], c0);
                c1 = fmaf(v.y, Wi1[49], c1);
            }
#pragma unroll
            for (int q = 0; q < 8; q++) {
                float4 v = hr[q];
                a0 = fmaf(v.x, Wh0[4 * q + 0], a0);
                a1 = fmaf(v.y, Wh0[4 * q + 1], a1);
                a0 = fmaf(v.z, Wh0[4 * q + 2], a0);
                a1 = fmaf(v.w, Wh0[4 * q + 3], a1);
                c0 = fmaf(v.x, Wh1[4 * q + 0], c0);
                c1 = fmaf(v.y, Wh1[4 * q + 1], c1);
                c0 = fmaf(v.z, Wh1[4 * q + 2], c0);
                c1 = fmaf(v.w, Wh1[4 * q + 3], c1);
            }
            h0 = tanh_fast(a0 + a1);
            h1 = tanh_fast(c0 + c1);
            hw[(p ^ 1) * 72 + dofs + u]      = h0;
            hw[(p ^ 1) * 72 + dofs + u + 16] = h1;
            __syncwarp();
        }

        // final hidden -> [n, dir*32 + unit]
        g_h2[(size_t)n * 64 + half * 32 + u]      = h0;
        g_h2[(size_t)n * 64 + half * 32 + u + 16] = h1;
        __syncwarp();  // reads of `buf` done before next iter restages it
        buf ^= 1;
    }
}

// ===========================================================================
// TEXT RNN (1/32 of the work) — R2 design kept: warp per (seq, dir),
// lane = unit, x staged in smem, h broadcast double-buffered.
// ===========================================================================
template <int TSTEPS, int PAIRS>
__global__ __launch_bounds__(PAIRS * 64)
void text_rnn_kernel(const float* __restrict__ X,
                     const float* __restrict__ wif, const float* __restrict__ whf,
                     const float* __restrict__ bif, const float* __restrict__ bhf,
                     const float* __restrict__ wib, const float* __restrict__ whb,
                     const float* __restrict__ bib, const float* __restrict__ bhb,
                     int nseq)
{
    __shared__ __align__(16) float xsl[PAIRS][TSTEPS][52];
    __shared__ __align__(16) float hbuf[2][PAIRS * 2][32];

    const int tid  = threadIdx.x;
    const int w    = tid >> 5;
    const int lane = tid & 31;
    const int p    = w >> 1;
    const int dir  = w & 1;
    const int nn   = blockIdx.x * PAIRS + p;

    {
        const int q = tid - p * 64;
        const float* xg = X + (size_t)nn * (TSTEPS * E_DIM);
        for (int i = q; i < TSTEPS * 52; i += 64) {
            int t = i / 52;
            int e = i - t * 52;
            xsl[p][t][e] = (e < E_DIM) ? xg[t * E_DIM + e] : 0.0f;
        }
    }
    __syncthreads();

    const float* wi = dir ? wib : wif;
    const float* wh = dir ? whb : whf;
    const float* bi = dir ? bib : bif;
    const float* bh = dir ? bhb : bhf;

    float Wi[52];
#pragma unroll
    for (int e = 0; e < E_DIM; e++) Wi[e] = __ldg(&wi[lane * E_DIM + e]);
    Wi[50] = 0.0f; Wi[51] = 0.0f;
    float Wh[32];
#pragma unroll
    for (int k = 0; k < H_DIM; k++) Wh[k] = __ldg(&wh[lane * H_DIM + k]);
    const float bias = __ldg(&bi[lane]) + __ldg(&bh[lane]);

    float h = 0.0f;
#pragma unroll 1
    for (int s = 0; s < TSTEPS; s++) {
        const int t   = dir ? (TSTEPS - 1 - s) : s;
        const int par = s & 1;
        hbuf[par][w][lane] = h;
        __syncwarp();

        float a0 = bias, a1 = 0.0f, a2 = 0.0f, a3 = 0.0f;
        const float4* xr = reinterpret_cast<const float4*>(xsl[p][t]);
#pragma unroll
        for (int q4 = 0; q4 < 13; q4++) {
            float4 v = xr[q4];
            a0 = fmaf(v.x, Wi[4 * q4 + 0], a0);
            a1 = fmaf(v.y, Wi[4 * q4 + 1], a1);
            a2 = fmaf(v.z, Wi[4 * q4 + 2], a2);
            a3 = fmaf(v.w, Wi[4 * q4 + 3], a3);
        }
        const float4* hr = reinterpret_cast<const float4*>(hbuf[par][w]);
#pragma unroll
        for (int q4 = 0; q4 < 8; q4++) {
            float4 v = hr[q4];
            a0 = fmaf(v.x, Wh[4 * q4 + 0], a0);
            a1 = fmaf(v.y, Wh[4 * q4 + 1], a1);
            a2 = fmaf(v.z, Wh[4 * q4 + 2], a2);
            a3 = fmaf(v.w, Wh[4 * q4 + 3], a3);
        }
        h = tanh_fast((a0 + a1) + (a2 + a3));
    }

    if (nn < nseq)
        g_hn[(size_t)nn * 64 + dir * 32 + lane] = h;
}

// ---------------------------------------------------------------------------
// Ragged segment mean/min/max over g_h2 (unchanged; small cost)
// ---------------------------------------------------------------------------
__global__ void seg_reduce_kernel(const int* __restrict__ te)
{
    const int b = blockIdx.x;
    const int c = threadIdx.x;   // 0..63
    __shared__ int s_off;
    if (c == 0) {
        int o = 0;
        for (int i = 0; i < b; i++) o += te[i];
        s_off = o;
    }
    __syncthreads();
    const int cnt = te[b];
    const float* hp = g_h2 + (size_t)s_off * 64 + c;
    float sm = 0.0f, mn = 3.402823466e38f, mx = -3.402823466e38f;
    for (int r = 0; r < cnt; r++) {
        float v = hp[(size_t)r * 64];
        sm += v;
        mn = fminf(mn, v);
        mx = fmaxf(mx, v);
    }
    const float inv = (cnt > 0) ? __fdividef(1.0f, (float)cnt) : 0.0f;
    g_red[b * 192 + c]       = sm * inv;
    g_red[b * 192 + 64 + c]  = mn;
    g_red[b * 192 + 128 + c] = mx;
}

// ---------------------------------------------------------------------------
// Head — rewritten: one block per batch row; warp computes 8 fc1 units with
// COALESCED weight loads (lane strides the 305-dim input), shfl-reduce.
// ---------------------------------------------------------------------------
__global__ __launch_bounds__(128)
void head_kernel(const float* __restrict__ nf,
                 const float* __restrict__ fc1_w, const float* __restrict__ fc1_b,
                 const float* __restrict__ fc2_w, const float* __restrict__ fc2_b,
                 float* __restrict__ out)
{
    __shared__ float xv[305];
    __shared__ float yp[4];
    const int row  = blockIdx.x;
    const int tid  = threadIdx.x;
    const int w    = tid >> 5;
    const int lane = tid & 31;

    for (int i = tid; i < 305; i += 128) {
        float v;
        if (i < 64)        v = g_hn[(size_t)row * 64 + i];
        else if (i < 113)  v = nf[(size_t)row * 49 + (i - 64)];
        else               v = g_red[(size_t)row * 192 + (i - 113)];
        xv[i] = v;
    }
    __syncthreads();

    float acc = 0.0f;
#pragma unroll
    for (int uu = 0; uu < 8; uu++) {
        const int u = w * 8 + uu;
        const float* wr = fc1_w + (size_t)u * 305;
        float ps = 0.0f;
        for (int k = lane; k < 305; k += 32)
            ps = fmaf(__ldg(wr + k), xv[k], ps);
#pragma unroll
        for (int o = 16; o > 0; o >>= 1) ps += __shfl_xor_sync(0xffffffffu, ps, o);
        if (lane == 0) {
            float y = tanh_fast(ps + __ldg(fc1_b + u));
            acc = fmaf(y, __ldg(fc2_w + u), acc);
        }
    }
    if (lane == 0) yp[w] = acc;
    __syncthreads();
    if (tid == 0) {
        float z = yp[0] + yp[1] + yp[2] + yp[3] + __ldg(fc2_b);
        out[row] = __fdividef(1.0f, 1.0f + __expf(-z));
    }
}

// ---------------------------------------------------------------------------
// Launch. Input ordering disambiguated at runtime (same as R2, which passed).
// Pure kernel launches — graph-capturable, allocation-free.
// ---------------------------------------------------------------------------
extern "C" void kernel_launch(void* const* d_in, const int* in_sizes, int n_in,
                              void* d_out, int out_size)
{
    int base_r1, base_r2, base_fc, idx_te;
    if (in_sizes[3] == B_SZ) {          // setup_inputs order
        idx_te = 3;  base_r1 = 4;  base_r2 = 12; base_fc = 20;
    } else {                            // reference signature order
        base_r1 = 3; base_r2 = 11; base_fc = 19; idx_te = n_in - 1;
    }

    const float* nf  = (const float*)d_in[0];
    const float* tf  = (const float*)d_in[1];
    const float* ttf = (const float*)d_in[2];
    const int*   te  = (const int*)d_in[idx_te];
#define FPTR(i) ((const float*)d_in[(i)])

    // Timeline RNN: persistent warps, grid-stride over 32768 sequences.
    timeline_rnn_kernel<<<888, 64>>>(
        ttf,
        FPTR(base_r2 + 0), FPTR(base_r2 + 1), FPTR(base_r2 + 2), FPTR(base_r2 + 3),
        FPTR(base_r2 + 4), FPTR(base_r2 + 5), FPTR(base_r2 + 6), FPTR(base_r2 + 7));

    // Text RNN: 512 seqs, 2 per block (4 warps), 256 blocks.
    text_rnn_kernel<T_TX, 2><<<B_SZ / 2, 128>>>(
        tf,
        FPTR(base_r1 + 0), FPTR(base_r1 + 1), FPTR(base_r1 + 2), FPTR(base_r1 + 3),
        FPTR(base_r1 + 4), FPTR(base_r1 + 5), FPTR(base_r1 + 6), FPTR(base_r1 + 7),
        B_SZ);

    // Segment mean/min/max.
    seg_reduce_kernel<<<B_SZ, 64>>>(te);

    // Head.
    head_kernel<<<B_SZ, 128>>>(
        nf,
        FPTR(base_fc + 0), FPTR(base_fc + 1), FPTR(base_fc + 2), FPTR(base_fc + 3),
        (float*)d_out);
#undef FPTR
}